// round 8
// baseline (speedup 1.0000x reference)
#include <cuda_runtime.h>
#include <cuda_bf16.h>
#include <math.h>
#include <stdint.h>

// Problem constants
constexpr int BATCH = 2;
constexpr int NPIX  = 65536;   // 256*256
constexpr int HI = 256, WI = 256;
constexpr int HL = 64,  WL = 64;
constexpr int CH = 128;

constexpr int MPIX  = 8;      // pixels per block
constexpr int MROWS = 32;     // 4 branches * 8 pixels
constexpr int NTHREADS = 256;

// Layer dims (K padded to mult of 16 for layer 1: 386 -> 400)
constexpr int KP1 = 400, N1 = 1024;
constexpr int KP2 = 1024, N2 = 512;
constexpr int KP3 = 512,  N3 = 256;
constexpr int KP4 = 256,  N4 = 128;

// smem activation pitches in u32 (k-pair units): K/2 + 4  (=> pitch mod 32 in {4,12}, bank-conflict free)
constexpr int P0 = KP1/2 + 4;   // 204
constexpr int P1 = KP2/2 + 4;   // 516
constexpr int P2 = KP3/2 + 4;   // 260
constexpr int P3 = KP4/2 + 4;   // 132
constexpr int P4 = N4/2  + 4;   // 68

// region0 holds X0/X2/X4 (hi+lo planes), region1 holds X1/X3
constexpr int R0_U32 = 2 * MROWS * P2;          // 16640 u32 (X2 is largest)
constexpr int R1_U32 = 2 * MROWS * P1;          // 33024 u32 (X1)
constexpr int SMEM_BYTES = (R0_U32 + R1_U32) * 4;  // 198656 B

#define DEVINL __device__ __forceinline__

// ---------------- weight fragment buffers (bf16 hi/lo, mma B-fragment order) ----------------
// layout: [ntile][ktile][lane] -> uint4 (hi_b0, hi_b1, lo_b0, lo_b1)
__device__ uint4 W1F[(N1/8) * (KP1/16) * 32];   // 128*25*32 = 102400
__device__ uint4 W2F[(N2/8) * (KP2/16) * 32];   // 64*64*32  = 131072
__device__ uint4 W3F[(N3/8) * (KP3/16) * 32];   // 32*32*32  = 32768
__device__ uint4 W4F[(N4/8) * (KP4/16) * 32];   // 16*16*32  = 8192

DEVINL void split2(float x, uint16_t& h, uint16_t& l) {
    __nv_bfloat16 hb = __float2bfloat16(x);
    float r = x - __bfloat162float(hb);
    __nv_bfloat16 lb = __float2bfloat16(r);
    h = __bfloat16_as_ushort(hb);
    l = __bfloat16_as_ushort(lb);
}
DEVINL float bfu(uint32_t bits16) {
    return __bfloat162float(__ushort_as_bfloat16((unsigned short)(bits16 & 0xffffu)));
}

// mma.sync m16n8k16 row.col f32 <- bf16*bf16 + f32
DEVINL void mma16816(float* d, const uint32_t* a, uint32_t b0, uint32_t b1) {
    asm("mma.sync.aligned.m16n8k16.row.col.f32.bf16.bf16.f32 "
        "{%0,%1,%2,%3}, {%4,%5,%6,%7}, {%8,%9}, {%0,%1,%2,%3};"
        : "+f"(d[0]), "+f"(d[1]), "+f"(d[2]), "+f"(d[3])
        : "r"(a[0]), "r"(a[1]), "r"(a[2]), "r"(a[3]), "r"(b0), "r"(b1));
}

// ---------------- prep kernel: fp32 weights -> hi/lo bf16 fragment layout ----------------
__global__ void prep_weights(const float* __restrict__ W, int K, int KP, int N, int sel) {
    uint4* out = (sel == 0) ? W1F : (sel == 1) ? W2F : (sel == 2) ? W3F : W4F;
    int KT = KP / 16;
    int total = (N / 8) * KT * 32;
    int idx = blockIdx.x * blockDim.x + threadIdx.x;
    if (idx >= total) return;
    int lane = idx & 31, tile = idx >> 5;
    int kt = tile % KT, ntile = tile / KT;
    int t4 = lane & 3, g = lane >> 2;
    int n = ntile * 8 + g;
    int k0 = kt * 16 + t4 * 2;
    int ks[4] = {k0, k0 + 1, k0 + 8, k0 + 9};
    uint16_t h[4], l[4];
    #pragma unroll
    for (int i = 0; i < 4; ++i) {
        float v = (ks[i] < K) ? W[(size_t)ks[i] * N + n] : 0.0f;
        split2(v, h[i], l[i]);
    }
    out[idx] = make_uint4((uint32_t)h[0] | ((uint32_t)h[1] << 16),
                          (uint32_t)h[2] | ((uint32_t)h[3] << 16),
                          (uint32_t)l[0] | ((uint32_t)l[1] << 16),
                          (uint32_t)l[2] | ((uint32_t)l[3] << 16));
}

// ---------------- one MLP layer via tensor-core MMAs ----------------
// Xin/Xout: u32 planes [hi(32 rows x P), lo(32 rows x P)] of bf16x2 packed along k.
// Each warp handles both 16-row m-tiles and NT n-tiles per pass; 8 warps span 8*NT ntiles/pass.
template<int KT, int NTILES, int NT, int PIN, int POUT>
DEVINL void mma_layer(const uint4* __restrict__ Wf, const float* __restrict__ bias,
                      const uint32_t* Xin, uint32_t* Xout, int lane, int warp)
{
    const int t4 = lane & 3, g = lane >> 2;
    const uint32_t* XinLo = Xin + MROWS * PIN;
    uint32_t* XoutLo = Xout + MROWS * POUT;
    constexpr int PASSES = NTILES / (8 * NT);

    #pragma unroll 1
    for (int pass = 0; pass < PASSES; ++pass) {
        const int ntile0 = (pass * 8 + warp) * NT;
        const uint4* wp = Wf + ((size_t)ntile0 * KT) * 32 + lane;

        float acc[2][NT][4];
        #pragma unroll
        for (int mt = 0; mt < 2; ++mt)
            #pragma unroll
            for (int nt = 0; nt < NT; ++nt)
                #pragma unroll
                for (int j = 0; j < 4; ++j) acc[mt][nt][j] = 0.0f;

        // double-buffered weight fragments
        uint4 wc[NT];
        #pragma unroll
        for (int nt = 0; nt < NT; ++nt) wc[nt] = wp[(size_t)nt * KT * 32];

        #pragma unroll 1
        for (int kt = 0; kt < KT; ++kt) {
            // A fragments (hi & lo) for both m-tiles, from smem
            uint32_t ah[2][4], al[2][4];
            const int cb = kt * 8 + t4;
            #pragma unroll
            for (int mt = 0; mt < 2; ++mt) {
                const int r0 = mt * 16 + g;
                ah[mt][0] = Xin[r0 * PIN + cb];
                ah[mt][1] = Xin[(r0 + 8) * PIN + cb];
                ah[mt][2] = Xin[r0 * PIN + cb + 4];
                ah[mt][3] = Xin[(r0 + 8) * PIN + cb + 4];
                al[mt][0] = XinLo[r0 * PIN + cb];
                al[mt][1] = XinLo[(r0 + 8) * PIN + cb];
                al[mt][2] = XinLo[r0 * PIN + cb + 4];
                al[mt][3] = XinLo[(r0 + 8) * PIN + cb + 4];
            }
            // prefetch next kt's weights
            uint4 wn[NT];
            const int ktn = (kt + 1 < KT) ? kt + 1 : kt;
            #pragma unroll
            for (int nt = 0; nt < NT; ++nt)
                wn[nt] = wp[((size_t)nt * KT + ktn) * 32];

            // 3-term split MMAs: hi*hi + hi*lo + lo*hi
            #pragma unroll
            for (int nt = 0; nt < NT; ++nt) {
                #pragma unroll
                for (int mt = 0; mt < 2; ++mt) {
                    mma16816(acc[mt][nt], ah[mt], wc[nt].x, wc[nt].y);
                    mma16816(acc[mt][nt], ah[mt], wc[nt].z, wc[nt].w);
                    mma16816(acc[mt][nt], al[mt], wc[nt].x, wc[nt].y);
                }
            }
            #pragma unroll
            for (int nt = 0; nt < NT; ++nt) wc[nt] = wn[nt];
        }

        // epilogue: bias + relu + hi/lo split, write bf16x2-packed (cols pair naturally)
        #pragma unroll
        for (int nt = 0; nt < NT; ++nt) {
            const int n0 = (ntile0 + nt) * 8;
            const float2 b2 = *reinterpret_cast<const float2*>(bias + n0 + 2 * t4);
            const int pi = n0 / 2 + t4;
            #pragma unroll
            for (int mt = 0; mt < 2; ++mt) {
                float d0 = fmaxf(acc[mt][nt][0] + b2.x, 0.0f);
                float d1 = fmaxf(acc[mt][nt][1] + b2.y, 0.0f);
                float d2 = fmaxf(acc[mt][nt][2] + b2.x, 0.0f);
                float d3 = fmaxf(acc[mt][nt][3] + b2.y, 0.0f);
                uint16_t h0,l0,h1,l1,h2,l2,h3,l3;
                split2(d0,h0,l0); split2(d1,h1,l1); split2(d2,h2,l2); split2(d3,h3,l3);
                const int r0 = mt * 16 + g;
                Xout  [r0 * POUT + pi]        = (uint32_t)h0 | ((uint32_t)h1 << 16);
                XoutLo[r0 * POUT + pi]        = (uint32_t)l0 | ((uint32_t)l1 << 16);
                Xout  [(r0 + 8) * POUT + pi]  = (uint32_t)h2 | ((uint32_t)h3 << 16);
                XoutLo[(r0 + 8) * POUT + pi]  = (uint32_t)l2 | ((uint32_t)l3 << 16);
            }
        }
    }
}

// ---------------- main fused kernel ----------------
__global__ __launch_bounds__(NTHREADS, 1)
void jiif_mma_kernel(
    const float* __restrict__ feat,      // [B,128,64,64]
    const float* __restrict__ coord,     // [B,N,2]
    const float* __restrict__ hr_guide,  // [B,128,256,256]
    const float* __restrict__ lr_guide,  // [B,128,64,64]
    const float* __restrict__ b1, const float* __restrict__ b2,
    const float* __restrict__ b3, const float* __restrict__ b4,
    const float* __restrict__ w5, const float* __restrict__ b5,
    float* __restrict__ out)             // [B,N,1]
{
    extern __shared__ uint32_t smem[];
    uint32_t* R0 = smem;          // X0 / X2 / X4
    uint32_t* R1 = smem + R0_U32; // X1 / X3

    const int tid  = threadIdx.x;
    const int lane = tid & 31;
    const int warp = tid >> 5;

    // ---------------- gather -> X0 (hi/lo bf16 planes, pitch P0) ----------------
    uint16_t* X0h16 = reinterpret_cast<uint16_t*>(R0);
    uint16_t* X0l16 = X0h16 + 2 * MROWS * P0;   // lo plane, u16 units
    for (int rr = 0; rr < 4; ++rr) {
        int row = warp * 4 + rr;
        int pi = row >> 2;
        int br = row & 3;

        int p = blockIdx.x * MPIX + pi;
        int b = p >> 16;

        float y = coord[(size_t)p * 2 + 0];
        float x = coord[(size_t)p * 2 + 1];

        int ihy = (int)floorf((y + 1.0f) * (0.5f * HI));
        int ihx = (int)floorf((x + 1.0f) * (0.5f * WI));
        bool vh = (ihy >= 0) & (ihy < HI) & (ihx >= 0) & (ihx < WI);
        int ihyc = min(max(ihy, 0), HI - 1);
        int ihxc = min(max(ihx, 0), WI - 1);

        float vx = (br & 2) ? 1.0f : -1.0f;
        float vy = (br & 1) ? 1.0f : -1.0f;
        float cy = y + vx * (1.0f / (float)HL);
        float cx = x + vy * (1.0f / (float)WL);
        int iy = (int)floorf((cy + 1.0f) * (0.5f * HL));
        int ix = (int)floorf((cx + 1.0f) * (0.5f * WL));
        bool v = (iy >= 0) & (iy < HL) & (ix >= 0) & (ix < WL);
        int iyc = min(max(iy, 0), HL - 1);
        int ixc = min(max(ix, 0), WL - 1);

        float qy = v ? (-1.0f + (2 * iyc + 1) * (1.0f / (float)HL)) : 0.0f;
        float qx = v ? (-1.0f + (2 * ixc + 1) * (1.0f / (float)WL)) : 0.0f;
        float rel_y = (y - qy) * (float)HL;
        float rel_x = (x - qx) * (float)WL;

        const float* featb = feat     + (size_t)b * CH * HL * WL;
        const float* hrb   = hr_guide + (size_t)b * CH * HI * WI;
        const float* lrb   = lr_guide + (size_t)b * CH * HL * WL;
        int fidx = iyc * WL + ixc;
        int hidx = ihyc * WI + ihxc;

        const int rb = row * (2 * P0);
        for (int c = lane; c < CH; c += 32) {
            float qf = v  ? featb[c * (HL * WL) + fidx] : 0.0f;
            float gh = vh ? hrb[c * (HI * WI) + hidx]   : 0.0f;
            float gl = v  ? lrb[c * (HL * WL) + fidx]   : 0.0f;
            uint16_t h, l;
            split2(qf, h, l);       X0h16[rb + c] = h;        X0l16[rb + c] = l;
            split2(gh, h, l);       X0h16[rb + 128 + c] = h;  X0l16[rb + 128 + c] = l;
            split2(gh - gl, h, l);  X0h16[rb + 256 + c] = h;  X0l16[rb + 256 + c] = l;
        }
        if (lane == 0) {
            uint16_t h, l;
            split2(rel_y, h, l); X0h16[rb + 384] = h; X0l16[rb + 384] = l;
            split2(rel_x, h, l); X0h16[rb + 385] = h; X0l16[rb + 385] = l;
        }
        // zero K padding 386..399 (both planes)
        for (int k = 386 + lane; k < KP1; k += 32) {
            X0h16[rb + k] = 0; X0l16[rb + k] = 0;
        }
    }
    __syncthreads();

    // ---------------- tensor-core MLP, ping-pong R0 <-> R1 ----------------
    mma_layer<KP1/16, N1/8, 4, P0, P1>(W1F, b1, R0, R1, lane, warp);  __syncthreads();
    mma_layer<KP2/16, N2/8, 4, P1, P2>(W2F, b2, R1, R0, lane, warp);  __syncthreads();
    mma_layer<KP3/16, N3/8, 4, P2, P3>(W3F, b3, R0, R1, lane, warp);  __syncthreads();
    mma_layer<KP4/16, N4/8, 2, P3, P4>(W4F, b4, R1, R0, lane, warp);  __syncthreads();

    // ---------------- layer 5 (128 -> 2): reconstruct fp32 from hi+lo planes ----------------
    float* l5 = reinterpret_cast<float*>(R1);   // X3 dead; 64-float scratch
    if (tid < MROWS * 2) {
        int row = tid >> 1;
        int c   = tid & 1;
        float acc = b5[c];
        const uint32_t* X4h = R0 + row * P4;
        const uint32_t* X4l = R0 + MROWS * P4 + row * P4;
        #pragma unroll 8
        for (int j = 0; j < N4 / 2; ++j) {
            uint32_t h = X4h[j], l = X4l[j];
            float e0 = bfu(h) + bfu(l);
            float e1 = bfu(h >> 16) + bfu(l >> 16);
            acc += e0 * w5[(2 * j) * 2 + c] + e1 * w5[(2 * j + 1) * 2 + c];
        }
        l5[row * 2 + c] = acc;
    }
    __syncthreads();

    // ---------------- softmax-weighted combine ----------------
    if (tid < MPIX) {
        int pi = tid;
        float v0[4], v1[4];
        #pragma unroll
        for (int br = 0; br < 4; ++br) {
            v0[br] = l5[(pi * 4 + br) * 2 + 0];
            v1[br] = l5[(pi * 4 + br) * 2 + 1];
        }
        float m = fmaxf(fmaxf(v1[0], v1[1]), fmaxf(v1[2], v1[3]));
        float num = 0.f, den = 0.f;
        #pragma unroll
        for (int br = 0; br < 4; ++br) {
            float e = expf(v1[br] - m);
            num += v0[br] * e;
            den += e;
        }
        out[(size_t)blockIdx.x * MPIX + pi] = num / den;
    }
}

extern "C" void kernel_launch(void* const* d_in, const int* in_sizes, int n_in,
                              void* d_out, int out_size) {
    const float* feat     = (const float*)d_in[0];
    const float* coord    = (const float*)d_in[1];
    const float* hr_guide = (const float*)d_in[2];
    const float* lr_guide = (const float*)d_in[3];
    const float* w1 = (const float*)d_in[4];
    const float* b1 = (const float*)d_in[5];
    const float* w2 = (const float*)d_in[6];
    const float* b2 = (const float*)d_in[7];
    const float* w3 = (const float*)d_in[8];
    const float* b3 = (const float*)d_in[9];
    const float* w4 = (const float*)d_in[10];
    const float* b4 = (const float*)d_in[11];
    const float* w5 = (const float*)d_in[12];
    const float* b5 = (const float*)d_in[13];
    float* out = (float*)d_out;

    // weight fragment prep (cheap; deterministic; same stream => ordered)
    prep_weights<<<((N1/8)*(KP1/16)*32 + 255) / 256, 256>>>(w1, 386,  KP1, N1, 0);
    prep_weights<<<((N2/8)*(KP2/16)*32 + 255) / 256, 256>>>(w2, 1024, KP2, N2, 1);
    prep_weights<<<((N3/8)*(KP3/16)*32 + 255) / 256, 256>>>(w3, 512,  KP3, N3, 2);
    prep_weights<<<((N4/8)*(KP4/16)*32 + 255) / 256, 256>>>(w4, 256,  KP4, N4, 3);

    cudaFuncSetAttribute(jiif_mma_kernel,
                         cudaFuncAttributeMaxDynamicSharedMemorySize, SMEM_BYTES);

    int nblocks = (BATCH * NPIX) / MPIX;   // 16384
    jiif_mma_kernel<<<nblocks, NTHREADS, SMEM_BYTES>>>(
        feat, coord, hr_guide, lr_guide,
        b1, b2, b3, b4, w5, b5, out);
}

// round 9
// speedup vs baseline: 1.0023x; 1.0023x over previous
#include <cuda_runtime.h>
#include <cuda_bf16.h>
#include <math.h>
#include <stdint.h>

// Problem constants
constexpr int BATCH = 2;
constexpr int NPIX  = 65536;   // 256*256
constexpr int HI = 256, WI = 256;
constexpr int HL = 64,  WL = 64;
constexpr int CH = 128;

constexpr int MPIX  = 8;      // pixels per block
constexpr int MROWS = 32;     // 4 branches * 8 pixels
constexpr int NTHREADS = 256;

// Layer dims (K padded to mult of 16 for layer 1: 386 -> 400)
constexpr int KP1 = 400, N1 = 1024;
constexpr int KP2 = 1024, N2 = 512;
constexpr int KP3 = 512,  N3 = 256;
constexpr int KP4 = 256,  N4 = 128;

// smem activation pitches in u32 (k-pair units): K/2 + 4  (=> pitch mod 32 in {4,12}, bank-conflict free)
constexpr int P0 = KP1/2 + 4;   // 204
constexpr int P1 = KP2/2 + 4;   // 516
constexpr int P2 = KP3/2 + 4;   // 260
constexpr int P3 = KP4/2 + 4;   // 132
constexpr int P4 = N4/2  + 4;   // 68

// region0 holds X0/X2/X4 (hi+lo planes), region1 holds X1/X3
constexpr int R0_U32 = 2 * MROWS * P2;          // 16640 u32 (X2 is largest)
constexpr int R1_U32 = 2 * MROWS * P1;          // 33024 u32 (X1)
constexpr int SMEM_BYTES = (R0_U32 + R1_U32) * 4;  // 198656 B

#define DEVINL __device__ __forceinline__

// ---------------- weight fragment buffers (bf16 hi/lo, mma B-fragment order) ----------------
// layout: [ntile][ktile][lane] -> uint4 (hi_b0, hi_b1, lo_b0, lo_b1)
__device__ uint4 W1F[(N1/8) * (KP1/16) * 32];   // 128*25*32 = 102400
__device__ uint4 W2F[(N2/8) * (KP2/16) * 32];   // 64*64*32  = 131072
__device__ uint4 W3F[(N3/8) * (KP3/16) * 32];   // 32*32*32  = 32768
__device__ uint4 W4F[(N4/8) * (KP4/16) * 32];   // 16*16*32  = 8192

DEVINL void split2(float x, uint16_t& h, uint16_t& l) {
    __nv_bfloat16 hb = __float2bfloat16(x);
    float r = x - __bfloat162float(hb);
    __nv_bfloat16 lb = __float2bfloat16(r);
    h = __bfloat16_as_ushort(hb);
    l = __bfloat16_as_ushort(lb);
}
DEVINL float bfu(uint32_t bits16) {
    return __bfloat162float(__ushort_as_bfloat16((unsigned short)(bits16 & 0xffffu)));
}

// mma.sync m16n8k16 row.col f32 <- bf16*bf16 + f32
DEVINL void mma16816(float* d, const uint32_t* a, uint32_t b0, uint32_t b1) {
    asm("mma.sync.aligned.m16n8k16.row.col.f32.bf16.bf16.f32 "
        "{%0,%1,%2,%3}, {%4,%5,%6,%7}, {%8,%9}, {%0,%1,%2,%3};"
        : "+f"(d[0]), "+f"(d[1]), "+f"(d[2]), "+f"(d[3])
        : "r"(a[0]), "r"(a[1]), "r"(a[2]), "r"(a[3]), "r"(b0), "r"(b1));
}

// ---------------- prep kernel: fp32 weights -> hi/lo bf16 fragment layout ----------------
__global__ void prep_weights(const float* __restrict__ W, int K, int KP, int N, int sel) {
    uint4* out = (sel == 0) ? W1F : (sel == 1) ? W2F : (sel == 2) ? W3F : W4F;
    int KT = KP / 16;
    int total = (N / 8) * KT * 32;
    int idx = blockIdx.x * blockDim.x + threadIdx.x;
    if (idx >= total) return;
    int lane = idx & 31, tile = idx >> 5;
    int kt = tile % KT, ntile = tile / KT;
    int t4 = lane & 3, g = lane >> 2;
    int n = ntile * 8 + g;
    int k0 = kt * 16 + t4 * 2;
    int ks[4] = {k0, k0 + 1, k0 + 8, k0 + 9};
    uint16_t h[4], l[4];
    #pragma unroll
    for (int i = 0; i < 4; ++i) {
        float v = (ks[i] < K) ? W[(size_t)ks[i] * N + n] : 0.0f;
        split2(v, h[i], l[i]);
    }
    out[idx] = make_uint4((uint32_t)h[0] | ((uint32_t)h[1] << 16),
                          (uint32_t)h[2] | ((uint32_t)h[3] << 16),
                          (uint32_t)l[0] | ((uint32_t)l[1] << 16),
                          (uint32_t)l[2] | ((uint32_t)l[3] << 16));
}

// ---------------- one MLP layer via tensor-core MMAs ----------------
// Xin/Xout: u32 planes [hi(32 rows x P), lo(32 rows x P)] of bf16x2 packed along k.
// Each warp handles both 16-row m-tiles and NT n-tiles per pass; 8 warps span 8*NT ntiles/pass.
template<int KT, int NTILES, int NT, int PIN, int POUT>
DEVINL void mma_layer(const uint4* __restrict__ Wf, const float* __restrict__ bias,
                      const uint32_t* Xin, uint32_t* Xout, int lane, int warp)
{
    const int t4 = lane & 3, g = lane >> 2;
    const uint32_t* XinLo = Xin + MROWS * PIN;
    uint32_t* XoutLo = Xout + MROWS * POUT;
    constexpr int PASSES = NTILES / (8 * NT);

    #pragma unroll 1
    for (int pass = 0; pass < PASSES; ++pass) {
        const int ntile0 = (pass * 8 + warp) * NT;
        const uint4* wp = Wf + ((size_t)ntile0 * KT) * 32 + lane;

        float acc[2][NT][4];
        #pragma unroll
        for (int mt = 0; mt < 2; ++mt)
            #pragma unroll
            for (int nt = 0; nt < NT; ++nt)
                #pragma unroll
                for (int j = 0; j < 4; ++j) acc[mt][nt][j] = 0.0f;

        // double-buffered weight fragments
        uint4 wc[NT];
        #pragma unroll
        for (int nt = 0; nt < NT; ++nt) wc[nt] = wp[(size_t)nt * KT * 32];

        #pragma unroll 1
        for (int kt = 0; kt < KT; ++kt) {
            // A fragments (hi & lo) for both m-tiles, from smem
            uint32_t ah[2][4], al[2][4];
            const int cb = kt * 8 + t4;
            #pragma unroll
            for (int mt = 0; mt < 2; ++mt) {
                const int r0 = mt * 16 + g;
                ah[mt][0] = Xin[r0 * PIN + cb];
                ah[mt][1] = Xin[(r0 + 8) * PIN + cb];
                ah[mt][2] = Xin[r0 * PIN + cb + 4];
                ah[mt][3] = Xin[(r0 + 8) * PIN + cb + 4];
                al[mt][0] = XinLo[r0 * PIN + cb];
                al[mt][1] = XinLo[(r0 + 8) * PIN + cb];
                al[mt][2] = XinLo[r0 * PIN + cb + 4];
                al[mt][3] = XinLo[(r0 + 8) * PIN + cb + 4];
            }
            // prefetch next kt's weights
            uint4 wn[NT];
            const int ktn = (kt + 1 < KT) ? kt + 1 : kt;
            #pragma unroll
            for (int nt = 0; nt < NT; ++nt)
                wn[nt] = wp[((size_t)nt * KT + ktn) * 32];

            // 3-term split MMAs: hi*hi + hi*lo + lo*hi
            #pragma unroll
            for (int nt = 0; nt < NT; ++nt) {
                #pragma unroll
                for (int mt = 0; mt < 2; ++mt) {
                    mma16816(acc[mt][nt], ah[mt], wc[nt].x, wc[nt].y);
                    mma16816(acc[mt][nt], ah[mt], wc[nt].z, wc[nt].w);
                    mma16816(acc[mt][nt], al[mt], wc[nt].x, wc[nt].y);
                }
            }
            #pragma unroll
            for (int nt = 0; nt < NT; ++nt) wc[nt] = wn[nt];
        }

        // epilogue: bias + relu + hi/lo split, write bf16x2-packed (cols pair naturally)
        #pragma unroll
        for (int nt = 0; nt < NT; ++nt) {
            const int n0 = (ntile0 + nt) * 8;
            const float2 b2 = *reinterpret_cast<const float2*>(bias + n0 + 2 * t4);
            const int pi = n0 / 2 + t4;
            #pragma unroll
            for (int mt = 0; mt < 2; ++mt) {
                float d0 = fmaxf(acc[mt][nt][0] + b2.x, 0.0f);
                float d1 = fmaxf(acc[mt][nt][1] + b2.y, 0.0f);
                float d2 = fmaxf(acc[mt][nt][2] + b2.x, 0.0f);
                float d3 = fmaxf(acc[mt][nt][3] + b2.y, 0.0f);
                uint16_t h0,l0,h1,l1,h2,l2,h3,l3;
                split2(d0,h0,l0); split2(d1,h1,l1); split2(d2,h2,l2); split2(d3,h3,l3);
                const int r0 = mt * 16 + g;
                Xout  [r0 * POUT + pi]        = (uint32_t)h0 | ((uint32_t)h1 << 16);
                XoutLo[r0 * POUT + pi]        = (uint32_t)l0 | ((uint32_t)l1 << 16);
                Xout  [(r0 + 8) * POUT + pi]  = (uint32_t)h2 | ((uint32_t)h3 << 16);
                XoutLo[(r0 + 8) * POUT + pi]  = (uint32_t)l2 | ((uint32_t)l3 << 16);
            }
        }
    }
}

// ---------------- main fused kernel ----------------
__global__ __launch_bounds__(NTHREADS, 1)
void jiif_mma_kernel(
    const float* __restrict__ feat,      // [B,128,64,64]
    const float* __restrict__ coord,     // [B,N,2]
    const float* __restrict__ hr_guide,  // [B,128,256,256]
    const float* __restrict__ lr_guide,  // [B,128,64,64]
    const float* __restrict__ b1, const float* __restrict__ b2,
    const float* __restrict__ b3, const float* __restrict__ b4,
    const float* __restrict__ w5, const float* __restrict__ b5,
    float* __restrict__ out)             // [B,N,1]
{
    extern __shared__ uint32_t smem[];
    uint32_t* R0 = smem;          // X0 / X2 / X4
    uint32_t* R1 = smem + R0_U32; // X1 / X3

    const int tid  = threadIdx.x;
    const int lane = tid & 31;
    const int warp = tid >> 5;

    // ---------------- gather -> X0 (hi/lo bf16 planes, pitch P0) ----------------
    uint16_t* X0h16 = reinterpret_cast<uint16_t*>(R0);
    uint16_t* X0l16 = X0h16 + 2 * MROWS * P0;   // lo plane, u16 units
    for (int rr = 0; rr < 4; ++rr) {
        int row = warp * 4 + rr;
        int pi = row >> 2;
        int br = row & 3;

        int p = blockIdx.x * MPIX + pi;
        int b = p >> 16;

        float y = coord[(size_t)p * 2 + 0];
        float x = coord[(size_t)p * 2 + 1];

        int ihy = (int)floorf((y + 1.0f) * (0.5f * HI));
        int ihx = (int)floorf((x + 1.0f) * (0.5f * WI));
        bool vh = (ihy >= 0) & (ihy < HI) & (ihx >= 0) & (ihx < WI);
        int ihyc = min(max(ihy, 0), HI - 1);
        int ihxc = min(max(ihx, 0), WI - 1);

        float vx = (br & 2) ? 1.0f : -1.0f;
        float vy = (br & 1) ? 1.0f : -1.0f;
        float cy = y + vx * (1.0f / (float)HL);
        float cx = x + vy * (1.0f / (float)WL);
        int iy = (int)floorf((cy + 1.0f) * (0.5f * HL));
        int ix = (int)floorf((cx + 1.0f) * (0.5f * WL));
        bool v = (iy >= 0) & (iy < HL) & (ix >= 0) & (ix < WL);
        int iyc = min(max(iy, 0), HL - 1);
        int ixc = min(max(ix, 0), WL - 1);

        float qy = v ? (-1.0f + (2 * iyc + 1) * (1.0f / (float)HL)) : 0.0f;
        float qx = v ? (-1.0f + (2 * ixc + 1) * (1.0f / (float)WL)) : 0.0f;
        float rel_y = (y - qy) * (float)HL;
        float rel_x = (x - qx) * (float)WL;

        const float* featb = feat     + (size_t)b * CH * HL * WL;
        const float* hrb   = hr_guide + (size_t)b * CH * HI * WI;
        const float* lrb   = lr_guide + (size_t)b * CH * HL * WL;
        int fidx = iyc * WL + ixc;
        int hidx = ihyc * WI + ihxc;

        const int rb = row * (2 * P0);
        for (int c = lane; c < CH; c += 32) {
            float qf = v  ? featb[c * (HL * WL) + fidx] : 0.0f;
            float gh = vh ? hrb[c * (HI * WI) + hidx]   : 0.0f;
            float gl = v  ? lrb[c * (HL * WL) + fidx]   : 0.0f;
            uint16_t h, l;
            split2(qf, h, l);       X0h16[rb + c] = h;        X0l16[rb + c] = l;
            split2(gh, h, l);       X0h16[rb + 128 + c] = h;  X0l16[rb + 128 + c] = l;
            split2(gh - gl, h, l);  X0h16[rb + 256 + c] = h;  X0l16[rb + 256 + c] = l;
        }
        if (lane == 0) {
            uint16_t h, l;
            split2(rel_y, h, l); X0h16[rb + 384] = h; X0l16[rb + 384] = l;
            split2(rel_x, h, l); X0h16[rb + 385] = h; X0l16[rb + 385] = l;
        }
        // zero K padding 386..399 (both planes)
        for (int k = 386 + lane; k < KP1; k += 32) {
            X0h16[rb + k] = 0; X0l16[rb + k] = 0;
        }
    }
    __syncthreads();

    // ---------------- tensor-core MLP, ping-pong R0 <-> R1 ----------------
    mma_layer<KP1/16, N1/8, 4, P0, P1>(W1F, b1, R0, R1, lane, warp);  __syncthreads();
    mma_layer<KP2/16, N2/8, 4, P1, P2>(W2F, b2, R1, R0, lane, warp);  __syncthreads();
    mma_layer<KP3/16, N3/8, 4, P2, P3>(W3F, b3, R0, R1, lane, warp);  __syncthreads();
    mma_layer<KP4/16, N4/8, 2, P3, P4>(W4F, b4, R1, R0, lane, warp);  __syncthreads();

    // ---------------- layer 5 (128 -> 2): reconstruct fp32 from hi+lo planes ----------------
    float* l5 = reinterpret_cast<float*>(R1);   // X3 dead; 64-float scratch
    if (tid < MROWS * 2) {
        int row = tid >> 1;
        int c   = tid & 1;
        float acc = b5[c];
        const uint32_t* X4h = R0 + row * P4;
        const uint32_t* X4l = R0 + MROWS * P4 + row * P4;
        #pragma unroll 8
        for (int j = 0; j < N4 / 2; ++j) {
            uint32_t h = X4h[j], l = X4l[j];
            float e0 = bfu(h) + bfu(l);
            float e1 = bfu(h >> 16) + bfu(l >> 16);
            acc += e0 * w5[(2 * j) * 2 + c] + e1 * w5[(2 * j + 1) * 2 + c];
        }
        l5[row * 2 + c] = acc;
    }
    __syncthreads();

    // ---------------- softmax-weighted combine ----------------
    if (tid < MPIX) {
        int pi = tid;
        float v0[4], v1[4];
        #pragma unroll
        for (int br = 0; br < 4; ++br) {
            v0[br] = l5[(pi * 4 + br) * 2 + 0];
            v1[br] = l5[(pi * 4 + br) * 2 + 1];
        }
        float m = fmaxf(fmaxf(v1[0], v1[1]), fmaxf(v1[2], v1[3]));
        float num = 0.f, den = 0.f;
        #pragma unroll
        for (int br = 0; br < 4; ++br) {
            float e = expf(v1[br] - m);
            num += v0[br] * e;
            den += e;
        }
        out[(size_t)blockIdx.x * MPIX + pi] = num / den;
    }
}

extern "C" void kernel_launch(void* const* d_in, const int* in_sizes, int n_in,
                              void* d_out, int out_size) {
    const float* feat     = (const float*)d_in[0];
    const float* coord    = (const float*)d_in[1];
    const float* hr_guide = (const float*)d_in[2];
    const float* lr_guide = (const float*)d_in[3];
    const float* w1 = (const float*)d_in[4];
    const float* b1 = (const float*)d_in[5];
    const float* w2 = (const float*)d_in[6];
    const float* b2 = (const float*)d_in[7];
    const float* w3 = (const float*)d_in[8];
    const float* b3 = (const float*)d_in[9];
    const float* w4 = (const float*)d_in[10];
    const float* b4 = (const float*)d_in[11];
    const float* w5 = (const float*)d_in[12];
    const float* b5 = (const float*)d_in[13];
    float* out = (float*)d_out;

    // weight fragment prep (cheap; deterministic; same stream => ordered)
    prep_weights<<<((N1/8)*(KP1/16)*32 + 255) / 256, 256>>>(w1, 386,  KP1, N1, 0);
    prep_weights<<<((N2/8)*(KP2/16)*32 + 255) / 256, 256>>>(w2, 1024, KP2, N2, 1);
    prep_weights<<<((N3/8)*(KP3/16)*32 + 255) / 256, 256>>>(w3, 512,  KP3, N3, 2);
    prep_weights<<<((N4/8)*(KP4/16)*32 + 255) / 256, 256>>>(w4, 256,  KP4, N4, 3);

    cudaFuncSetAttribute(jiif_mma_kernel,
                         cudaFuncAttributeMaxDynamicSharedMemorySize, SMEM_BYTES);

    int nblocks = (BATCH * NPIX) / MPIX;   // 16384
    jiif_mma_kernel<<<nblocks, NTHREADS, SMEM_BYTES>>>(
        feat, coord, hr_guide, lr_guide,
        b1, b2, b3, b4, w5, b5, out);
}